// round 15
// baseline (speedup 1.0000x reference)
#include <cuda_runtime.h>
#include <cuda_bf16.h>

#define GG   256      // graphs
#define DD   128      // feature dim
#define ROWS_PER_WARP 128
#define ACC_THREADS   256   // 8 warps per CTA
#define FIN_CTAS 64         // last-to-finish CTAs run the MLP head
#define GPB 4               // graphs per finalizer CTA (FIN_CTAS*GPB == GG)

// Zero-initialized at module load; fused epilogue re-zeros after consuming,
// so the invariant "scratch is zero at kernel start" holds on every replay.
__device__ float g_sums[GG * DD];
__device__ float g_counts[GG];
__device__ int   g_done;   // CTAs finished with accumulation
__device__ int   g_fin;    // finalizer CTAs finished with the MLP

__device__ __forceinline__ int load_g(const void* batch, long long i, int is64) {
    if (is64) return (int)((const long long*)batch)[i];
    return ((const int*)batch)[i];
}

__device__ __forceinline__ void flush_seg(int g, float4 acc, int cnt, int lane) {
    if (cnt == 0) return;
    float* s = g_sums + (long long)g * DD + lane * 4;
    atomicAdd(s + 0, acc.x);
    atomicAdd(s + 1, acc.y);
    atomicAdd(s + 2, acc.z);
    atomicAdd(s + 3, acc.w);
    if (lane == 0) atomicAdd(&g_counts[g], (float)cnt);
}

// Fused kernel: streaming segment-sum + last-64-CTA MLP epilogue.
// __launch_bounds__(256, 8): cap regs at 32 so 8 CTAs (64 warps) fit per SM —
// R10 showed 56 regs + 35KB smem halved occupancy and cost 6% of HBM BW.
// Smem is ~2.3KB (no W1 staging; epilogue reads W1 from L2, overlapped with
// the HBM drain tail).
__global__ void __launch_bounds__(ACC_THREADS, 8)
fused_kernel(const float4* __restrict__ x4,
             const void* __restrict__ batch, int N,
             int total_ctas,
             const float* __restrict__ W1,
             const float* __restrict__ b1,
             const float* __restrict__ W2,
             const float* __restrict__ b2,
             float* __restrict__ out) {
    __shared__ float sum_s[GPB * DD];   // 2 KB
    __shared__ float cnt_s[GPB];
    __shared__ float wpart[8];
    __shared__ int   s_ticket;

    // ------------------- accumulation phase -------------------
    {
        // dtype probe: int32 word N-1 is the high half of int64 element
        // 999,999 (=0) if batch is int64, but the sorted max (>0) if int32.
        const int is64 = (((const int*)batch)[N - 1] == 0);
        const int lane = threadIdx.x & 31;
        const long long warp = (long long)(blockIdx.x * (ACC_THREADS / 32)) + (threadIdx.x >> 5);
        long long r0 = warp * ROWS_PER_WARP;
        if (r0 < N) {                       // no early return: CTA must reach the ticket
            long long r1 = r0 + ROWS_PER_WARP;
            if (r1 > N) r1 = N;

            const int gfirst = load_g(batch, r0, is64);
            const int glast  = load_g(batch, r1 - 1, is64);

            if (gfirst == glast) {
                // fast path: whole block in one segment. 4x unroll (MLP=4)
                // fits the 32-reg cap; 64 warps/SM keep HBM saturated.
                float4 acc = make_float4(0.f, 0.f, 0.f, 0.f);
                long long r = r0;
                for (; r + 4 <= r1; r += 4) {
                    float4 v0 = __ldcs(&x4[(r    ) * 32 + lane]);
                    float4 v1 = __ldcs(&x4[(r + 1) * 32 + lane]);
                    float4 v2 = __ldcs(&x4[(r + 2) * 32 + lane]);
                    float4 v3 = __ldcs(&x4[(r + 3) * 32 + lane]);
                    acc.x += (v0.x + v1.x) + (v2.x + v3.x);
                    acc.y += (v0.y + v1.y) + (v2.y + v3.y);
                    acc.z += (v0.z + v1.z) + (v2.z + v3.z);
                    acc.w += (v0.w + v1.w) + (v2.w + v3.w);
                }
                for (; r < r1; r++) {
                    float4 v = __ldcs(&x4[r * 32 + lane]);
                    acc.x += v.x; acc.y += v.y; acc.z += v.z; acc.w += v.w;
                }
                flush_seg(gfirst, acc, (int)(r1 - r0), lane);
            } else {
                // slow path: boundary inside this block (~2% of warps)
                float4 acc = make_float4(0.f, 0.f, 0.f, 0.f);
                int cnt = 0;
                int cur = gfirst;
                long long r = r0;
                for (; r + 4 <= r1; r += 4) {
                    int ga = load_g(batch, r,     is64);
                    int gd = load_g(batch, r + 3, is64);
                    float4 v0 = __ldcs(&x4[(r    ) * 32 + lane]);
                    float4 v1 = __ldcs(&x4[(r + 1) * 32 + lane]);
                    float4 v2 = __ldcs(&x4[(r + 2) * 32 + lane]);
                    float4 v3 = __ldcs(&x4[(r + 3) * 32 + lane]);
                    if (ga == cur && gd == cur) {
                        acc.x += (v0.x + v1.x) + (v2.x + v3.x);
                        acc.y += (v0.y + v1.y) + (v2.y + v3.y);
                        acc.z += (v0.z + v1.z) + (v2.z + v3.z);
                        acc.w += (v0.w + v1.w) + (v2.w + v3.w);
                        cnt += 4;
                    } else {
                        int gs[4];
                        gs[0] = ga;
                        gs[1] = load_g(batch, r + 1, is64);
                        gs[2] = load_g(batch, r + 2, is64);
                        gs[3] = gd;
                        float4 vs[4] = {v0, v1, v2, v3};
                        #pragma unroll
                        for (int k = 0; k < 4; k++) {
                            if (gs[k] != cur) {
                                flush_seg(cur, acc, cnt, lane);
                                acc = make_float4(0.f, 0.f, 0.f, 0.f);
                                cnt = 0;
                                cur = gs[k];
                            }
                            acc.x += vs[k].x; acc.y += vs[k].y;
                            acc.z += vs[k].z; acc.w += vs[k].w;
                            cnt++;
                        }
                    }
                }
                for (; r < r1; r++) {
                    int g = load_g(batch, r, is64);
                    float4 v = __ldcs(&x4[r * 32 + lane]);
                    if (g != cur) {
                        flush_seg(cur, acc, cnt, lane);
                        acc = make_float4(0.f, 0.f, 0.f, 0.f);
                        cnt = 0;
                        cur = g;
                    }
                    acc.x += v.x; acc.y += v.y; acc.z += v.z; acc.w += v.w;
                    cnt++;
                }
                flush_seg(cur, acc, cnt, lane);
            }
        }
    }

    // ------------------- completion ticketing -------------------
    __syncthreads();
    if (threadIdx.x == 0) {
        __threadfence();                       // sums visible before the count
        s_ticket = atomicAdd(&g_done, 1);
    }
    __syncthreads();
    const int ticket = s_ticket;
    const int fin_base = total_ctas - FIN_CTAS;
    if (ticket < fin_base) return;             // not among the last 64 finishers

    // ------------------- MLP epilogue (last 64 CTAs) -------------------
    const int fb = ticket - fin_base;          // 0..63 -> graphs [fb*4, fb*4+4)
    const int gbase = fb * GPB;
    const int t = threadIdx.x;

    // Wait for ALL CTAs' sums (spin overlaps the HBM drain tail).
    if (t == 0) {
        while (true) {
            int v;
            asm volatile("ld.global.acquire.gpu.s32 %0, [%1];"
                         : "=r"(v) : "l"(&g_done));
            if (v == total_ctas) break;
            __nanosleep(64);
        }
    }
    __syncthreads();

    // Stage this CTA's 4 graphs of raw sums + counts into smem.
    #pragma unroll
    for (int i = 0; i < 2; i++) {
        int idx = t + i * 256;                 // 0..511
        sum_s[idx] = __ldcg(&g_sums[gbase * DD + idx]);
    }
    if (t < GPB) cnt_s[t] = __ldcg(&g_counts[gbase + t]);
    __syncthreads();

    // Restore zero-invariant for the next replay.
    #pragma unroll
    for (int i = 0; i < 2; i++)
        g_sums[gbase * DD + t + i * 256] = 0.0f;
    if (t < GPB) g_counts[gbase + t] = 0.0f;

    // Thread t: graph q = t>>6, hidden unit j = t&63, full 128-d chain.
    // W1 from L2 (coalesced across j; 4 graph-groups share each row via L1).
    const int j = t & 63;
    const int q = t >> 6;
    float h = 0.0f;
    #pragma unroll 8
    for (int d = 0; d < DD; d++)
        h = fmaf(sum_s[q * DD + d], __ldg(&W1[d * 64 + j]), h);

    float inv = 1.0f / cnt_s[q];
    float hv = fmaxf(h * inv + b1[j], 0.0f) * W2[j];

    // Layer-2 reduce: graph q spans warps 2q, 2q+1.
    const int warp = t >> 5;
    const int lane = t & 31;
    #pragma unroll
    for (int s = 16; s > 0; s >>= 1)
        hv += __shfl_down_sync(0xffffffffu, hv, s);
    if (lane == 0) wpart[warp] = hv;
    __syncthreads();
    if (t < GPB) out[gbase + t] = wpart[2 * t] + wpart[2 * t + 1] + b2[0];

    // Reset ticket counters: last finalizer does it, strictly after all
    // spinners have exited (they increment g_fin only after their compute).
    __syncthreads();
    if (t == 0) {
        __threadfence();
        int f = atomicAdd(&g_fin, 1);
        if (f == FIN_CTAS - 1) {
            g_done = 0;
            g_fin  = 0;
            __threadfence();
        }
    }
}

extern "C" void kernel_launch(void* const* d_in, const int* in_sizes, int n_in,
                              void* d_out, int out_size) {
    const float* x     = (const float*)d_in[0];
    const void*  batch = d_in[1];
    const float* W1    = (const float*)d_in[2];
    const float* b1    = (const float*)d_in[3];
    const float* W2    = (const float*)d_in[4];
    const float* b2    = (const float*)d_in[5];
    float* out = (float*)d_out;

    const int N = in_sizes[0] / DD;   // 2,000,000

    int warps = (N + ROWS_PER_WARP - 1) / ROWS_PER_WARP;
    int ctas  = (warps + (ACC_THREADS / 32) - 1) / (ACC_THREADS / 32);
    fused_kernel<<<ctas, ACC_THREADS>>>((const float4*)x, batch, N, ctas,
                                        W1, b1, W2, b2, out);
}

// round 16
// speedup vs baseline: 1.0891x; 1.0891x over previous
#include <cuda_runtime.h>
#include <cuda_bf16.h>

#define GG   256      // graphs
#define DD   128      // feature dim
#define ROWS_PER_WARP 128
#define ACC_THREADS   256   // 8 warps per CTA
#define FIN_CTAS 128        // single wave on 148 SMs; 2 graphs per CTA

// Zero-initialized at module load; finalize_kernel re-zeros after consuming,
// so the invariant "scratch is zero at accum launch" holds on every replay.
__device__ float g_sums[GG * DD];
__device__ float g_counts[GG];

__device__ __forceinline__ int load_g(const void* batch, long long i, int is64) {
    if (is64) return (int)((const long long*)batch)[i];
    return ((const int*)batch)[i];
}

__device__ __forceinline__ void flush_seg(int g, float4 acc, int cnt, int lane) {
    if (cnt == 0) return;
    float* s = g_sums + (long long)g * DD + lane * 4;
    atomicAdd(s + 0, acc.x);
    atomicAdd(s + 1, acc.y);
    atomicAdd(s + 2, acc.z);
    atomicAdd(s + 3, acc.w);
    if (lane == 0) atomicAdd(&g_counts[g], (float)cnt);
}

// Streaming segment-sum — byte-identical to the proven R9 version (MLP=8
// fast path, no launch bounds; fused variants with lower per-warp MLP
// measured 5-10% less DRAM throughput).
__global__ void accum_kernel(const float4* __restrict__ x4,
                             const void* __restrict__ batch, int N) {
    // dtype probe: int32 word N-1 is the high half of int64 element 999,999 (=0)
    // if batch is int64, but the sorted max (>0) if int32.
    const int is64 = (((const int*)batch)[N - 1] == 0);
    const int lane = threadIdx.x & 31;
    const long long warp = (long long)(blockIdx.x * (ACC_THREADS / 32)) + (threadIdx.x >> 5);
    long long r0 = warp * ROWS_PER_WARP;
    if (r0 >= N) return;
    long long r1 = r0 + ROWS_PER_WARP;
    if (r1 > N) r1 = N;

    const int gfirst = load_g(batch, r0, is64);
    const int glast  = load_g(batch, r1 - 1, is64);

    if (gfirst == glast) {
        // ---- fast path: whole block in one segment, 8 LDG.128 in flight ----
        float4 acc = make_float4(0.f, 0.f, 0.f, 0.f);
        long long r = r0;
        for (; r + 8 <= r1; r += 8) {
            float4 v[8];
            #pragma unroll
            for (int k = 0; k < 8; k++)
                v[k] = __ldcs(&x4[(r + k) * 32 + lane]);   // evict-first stream
            #pragma unroll
            for (int k = 0; k < 8; k++) {
                acc.x += v[k].x; acc.y += v[k].y;
                acc.z += v[k].z; acc.w += v[k].w;
            }
        }
        for (; r < r1; r++) {
            float4 v = __ldcs(&x4[r * 32 + lane]);
            acc.x += v.x; acc.y += v.y; acc.z += v.z; acc.w += v.w;
        }
        flush_seg(gfirst, acc, (int)(r1 - r0), lane);
        return;
    }

    // ---- slow path: segment boundary inside this block (~2% of warps) ----
    float4 acc = make_float4(0.f, 0.f, 0.f, 0.f);
    int cnt = 0;
    int cur = gfirst;

    long long r = r0;
    for (; r + 4 <= r1; r += 4) {
        int ga = load_g(batch, r,     is64);
        int gd = load_g(batch, r + 3, is64);
        float4 v0 = __ldcs(&x4[(r    ) * 32 + lane]);
        float4 v1 = __ldcs(&x4[(r + 1) * 32 + lane]);
        float4 v2 = __ldcs(&x4[(r + 2) * 32 + lane]);
        float4 v3 = __ldcs(&x4[(r + 3) * 32 + lane]);
        if (ga == cur && gd == cur) {
            acc.x += (v0.x + v1.x) + (v2.x + v3.x);
            acc.y += (v0.y + v1.y) + (v2.y + v3.y);
            acc.z += (v0.z + v1.z) + (v2.z + v3.z);
            acc.w += (v0.w + v1.w) + (v2.w + v3.w);
            cnt += 4;
        } else {
            int gs[4];
            gs[0] = ga;
            gs[1] = load_g(batch, r + 1, is64);
            gs[2] = load_g(batch, r + 2, is64);
            gs[3] = gd;
            float4 vs[4] = {v0, v1, v2, v3};
            #pragma unroll
            for (int k = 0; k < 4; k++) {
                if (gs[k] != cur) {
                    flush_seg(cur, acc, cnt, lane);
                    acc = make_float4(0.f, 0.f, 0.f, 0.f);
                    cnt = 0;
                    cur = gs[k];
                }
                acc.x += vs[k].x; acc.y += vs[k].y;
                acc.z += vs[k].z; acc.w += vs[k].w;
                cnt++;
            }
        }
    }
    for (; r < r1; r++) {
        int g = load_g(batch, r, is64);
        float4 v = __ldcs(&x4[r * 32 + lane]);
        if (g != cur) {
            flush_seg(cur, acc, cnt, lane);
            acc = make_float4(0.f, 0.f, 0.f, 0.f);
            cnt = 0;
            cur = g;
        }
        acc.x += v.x; acc.y += v.y; acc.z += v.z; acc.w += v.w;
        cnt++;
    }
    flush_seg(cur, acc, cnt, lane);
}

// Mean + MLP head. SINGLE WAVE: 128 CTAs (<=148 SMs), 256 threads, 2 graphs
// per CTA. Thread t: graph q = t>>7, half h = (t>>6)&1, unit j = t&63;
// 64-FMA LDS chain per thread (halves combined in smem) — half the critical
// path of the 128-chain version, and no second wave to re-pay the W1-fetch ramp.
// W1 staged in smem via 8 independent LDG.128/thread, concurrent with raw-sum
// loads; 1/count folded in after layer 1 (linearity) so g_counts is off the
// critical path. Re-zeros its graphs' scratch for the next replay.
__global__ void finalize_kernel(const float* __restrict__ W1,
                                const float* __restrict__ b1,
                                const float* __restrict__ W2,
                                const float* __restrict__ b2,
                                float* __restrict__ out) {
    const int t = threadIdx.x;         // 0..255
    const int gbase = blockIdx.x * 2;  // graphs gbase, gbase+1
    __shared__ float w1s[DD * 64];     // 32 KB
    __shared__ float sum_s[2 * DD];    // raw sums for 2 graphs
    __shared__ float hh[256];
    __shared__ float wpart[8];
    __shared__ float cnt_s[2];

    // Independent prefetches — all pipelined, nothing serial.
    const float4* W14 = (const float4*)W1;     // 2048 float4
    float4 wv[8];
    #pragma unroll
    for (int i = 0; i < 8; i++) wv[i] = W14[t + i * 256];
    sum_s[t] = g_sums[gbase * DD + t];         // 256 floats = 2 graphs
    if (t < 2) cnt_s[t] = g_counts[gbase + t];
    #pragma unroll
    for (int i = 0; i < 8; i++) ((float4*)w1s)[t + i * 256] = wv[i];
    __syncthreads();

    // restore zero-invariant for the next replay (all reads done above)
    g_sums[gbase * DD + t] = 0.0f;
    if (t < 2) g_counts[gbase + t] = 0.0f;

    // Layer 1, half-split: q = graph, h = d-half, j = hidden unit.
    const int j = t & 63;
    const int h = (t >> 6) & 1;
    const int q = t >> 7;
    const int dbase = h * 64;
    float acc = 0.0f;
    #pragma unroll
    for (int d0 = 0; d0 < 64; d0++) {
        int d = dbase + d0;
        acc = fmaf(sum_s[q * DD + d], w1s[d * 64 + j], acc);  // conflict-free LDS
    }
    hh[t] = acc;
    __syncthreads();

    // Combine halves + bias + relu + W2, then per-graph reduce (2 warps/graph).
    if (t < 128) {
        const int qq = t >> 6;
        const int jj = t & 63;
        float inv = 1.0f / cnt_s[qq];
        float hv = (hh[qq * 128 + jj] + hh[qq * 128 + 64 + jj]) * inv + b1[jj];
        hv = fmaxf(hv, 0.0f) * W2[jj];
        #pragma unroll
        for (int s = 16; s > 0; s >>= 1)
            hv += __shfl_down_sync(0xffffffffu, hv, s);
        if ((t & 31) == 0) wpart[t >> 5] = hv;
    }
    __syncthreads();
    if (t < 2) out[gbase + t] = wpart[2 * t] + wpart[2 * t + 1] + b2[0];
}

extern "C" void kernel_launch(void* const* d_in, const int* in_sizes, int n_in,
                              void* d_out, int out_size) {
    const float* x     = (const float*)d_in[0];
    const void*  batch = d_in[1];
    const float* W1    = (const float*)d_in[2];
    const float* b1    = (const float*)d_in[3];
    const float* W2    = (const float*)d_in[4];
    const float* b2    = (const float*)d_in[5];
    float* out = (float*)d_out;

    const int N = in_sizes[0] / DD;   // 2,000,000

    int warps = (N + ROWS_PER_WARP - 1) / ROWS_PER_WARP;
    int ctas  = (warps + (ACC_THREADS / 32) - 1) / (ACC_THREADS / 32);
    accum_kernel<<<ctas, ACC_THREADS>>>((const float4*)x, batch, N);

    finalize_kernel<<<FIN_CTAS, 256>>>(W1, b1, W2, b2, out);
}